// round 16
// baseline (speedup 1.0000x reference)
#include <cuda_runtime.h>
#include <cuda_fp16.h>
#include <cstdint>

#define D_MODEL 1024
#define HEADS   16
#define DH      64
#define BATCH   4
#define SEQ     2048
#define NTOK    (BATCH * SEQ)   // 8192

// Q pre-scale: 0.125 (dh^-1/2) * log2(e)  -> softmax done in base-2 domain
#define QSCALE 0.1803368801111204f

// ---------------- scratch (device globals; no runtime alloc allowed) -------
__device__ __half g_xh[(size_t)NTOK * D_MODEL];
__device__ __half g_qkvh[(size_t)NTOK * 3 * D_MODEL]; // [8192,3072]
__device__ __half g_ch[(size_t)NTOK * D_MODEL];       // ctx
__device__ __half g_wqh[(size_t)3 * D_MODEL * D_MODEL]; // Wqkv^T [3072,1024]
__device__ __half g_wph[(size_t)D_MODEL * D_MODEL];     // Wproj^T

// ---------------------------------------------------------------------------
// Helpers (portable ISA only — .target sm_103 without 'a')
// ---------------------------------------------------------------------------
__device__ __forceinline__ uint32_t smem_u32(const void* p) {
    uint32_t a;
    asm("{ .reg .u64 t; cvta.to.shared.u64 t, %1; cvt.u32.u64 %0, t; }"
        : "=r"(a) : "l"(p));
    return a;
}
__device__ __forceinline__ void cp16(uint32_t saddr, const void* gaddr) {
    asm volatile("cp.async.cg.shared.global [%0], [%1], 16;"
        :: "r"(saddr), "l"(gaddr));
}
#define CP_COMMIT() asm volatile("cp.async.commit_group;")
#define CP_WAIT(n)  asm volatile("cp.async.wait_group %0;" :: "n"(n))

__device__ __forceinline__ void ldm4(uint32_t* r, uint32_t a) {
    asm volatile("ldmatrix.sync.aligned.m8n8.x4.shared.b16 {%0,%1,%2,%3}, [%4];"
        : "=r"(r[0]), "=r"(r[1]), "=r"(r[2]), "=r"(r[3]) : "r"(a));
}
__device__ __forceinline__ void ldm4t(uint32_t* r, uint32_t a) {
    asm volatile("ldmatrix.sync.aligned.m8n8.x4.trans.shared.b16 {%0,%1,%2,%3}, [%4];"
        : "=r"(r[0]), "=r"(r[1]), "=r"(r[2]), "=r"(r[3]) : "r"(a));
}
__device__ __forceinline__ void mma16816(float* c, const uint32_t* a, const uint32_t* b) {
    asm volatile(
        "mma.sync.aligned.m16n8k16.row.col.f32.f16.f16.f32 "
        "{%0,%1,%2,%3}, {%4,%5,%6,%7}, {%8,%9}, {%0,%1,%2,%3};"
        : "+f"(c[0]), "+f"(c[1]), "+f"(c[2]), "+f"(c[3])
        : "r"(a[0]), "r"(a[1]), "r"(a[2]), "r"(a[3]), "r"(b[0]), "r"(b[1]));
}

__device__ __forceinline__ uint32_t pk_hi2(float a, float b) {
    __half2 hh = __floats2half2_rn(a, b);
    return *reinterpret_cast<uint32_t*>(&hh);
}

// Single-MUFU exp2 (guaranteed ex2.approx regardless of fast-math flags)
__device__ __forceinline__ float ex2(float x) {
    float y;
    asm("ex2.approx.f32 %0, %1;" : "=f"(y) : "f"(x));
    return y;
}

// swizzled offset in a 32-col f16 tile (64B rows, 4 chunks)
__device__ __forceinline__ uint32_t gswz(int row, int chunk) {
    return (uint32_t)row * 64 + ((chunk ^ ((row >> 1) & 3)) << 4);
}
// swizzled offset in a 64-col f16 tile (128B rows, 8 chunks)
__device__ __forceinline__ uint32_t aswz(int row, int chunk) {
    return (uint32_t)row * 128 + ((chunk ^ (row & 7)) << 4);
}

// ---------------------------------------------------------------------------
// Conversion kernels
// ---------------------------------------------------------------------------
__global__ __launch_bounds__(256) void convert_hi(
    const float4* __restrict__ in, uint2* __restrict__ hi, int n4)
{
    int i = blockIdx.x * 256 + threadIdx.x;
    if (i >= n4) return;
    float4 v = in[i];
    hi[i] = make_uint2(pk_hi2(v.x, v.y), pk_hi2(v.z, v.w));
}

__global__ __launch_bounds__(256) void transpose_hi(
    const float* __restrict__ W, int K, int N, __half* __restrict__ Thi)
{
    __shared__ float tile[32][33];
    int kb = blockIdx.y * 32, nb = blockIdx.x * 32;
    int tx = threadIdx.x, ty = threadIdx.y;
#pragma unroll
    for (int i = 0; i < 32; i += 8)
        tile[ty + i][tx] = W[(size_t)(kb + ty + i) * N + nb + tx];
    __syncthreads();
#pragma unroll
    for (int i = 0; i < 32; i += 8) {
        int n = nb + ty + i, k = kb + tx;
        Thi[(size_t)n * K + k] = __float2half_rn(tile[tx][ty + i]);
    }
}

// ---------------------------------------------------------------------------
// HMMA fp16 GEMM: C = A[M,K] @ B[N,K]^T + bias  (fp32 accumulate)
// out_mode 0: fp32 C. out_mode 1: fp16 out, cols<1024 scaled by QSCALE (QKV).
// 128x128 CTA tile, K-chunk 32, swizzled 64B rows, 4-stage, 1 sync/iter.
// ---------------------------------------------------------------------------
#define TILEB    8192
#define NSTAGE   4
#define STB      (2 * TILEB)
#define GEMM_SMEM (NSTAGE * STB)   // 65536

__global__ __launch_bounds__(256, 2) void gemm_mma_f16(
    int M, int N, int K,
    const __half* __restrict__ A,
    const __half* __restrict__ B,
    const float* __restrict__ bias,
    float* __restrict__ C,
    __half* __restrict__ Ch,
    int out_mode)
{
    extern __shared__ char smem[];
    const uint32_t sb = smem_u32(smem);

    const int tid = threadIdx.x;
    const int lane = tid & 31;
    const int wid = tid >> 5;
    const int warpM = wid & 3;
    const int warpN = wid >> 2;

    const size_t arow0 = (size_t)blockIdx.y * 128 * K;
    const size_t brow0 = (size_t)blockIdx.x * 128 * K;

    const int ldRow = tid >> 2;
    const int ldCh  = tid & 3;

    float acc[2][8][4] = {};
    const int NCH = K / 32;

    auto issue = [&](int c, int s) {
        const int k0 = c * 32;
        const uint32_t st = sb + s * STB;
#pragma unroll
        for (int p = 0; p < 2; p++) {
            const int row = ldRow + p * 64;
            const uint32_t soff = gswz(row, ldCh);
            const size_t goff = (size_t)row * K + k0 + ldCh * 8;
            cp16(st + soff, A + arow0 + goff);
            cp16(st + TILEB + soff, B + brow0 + goff);
        }
    };

    issue(0, 0); CP_COMMIT();
    issue(1, 1); CP_COMMIT();
    issue(2, 2); CP_COMMIT();

    for (int c = 0; c < NCH; c++) {
        if (c + 2 < NCH) CP_WAIT(2);
        else if (c + 1 < NCH) CP_WAIT(1);
        else CP_WAIT(0);
        __syncthreads();
        if (c + 3 < NCH) { issue(c + 3, (c + 3) % NSTAGE); CP_COMMIT(); }

        const uint32_t st = sb + (c % NSTAGE) * STB;
        const uint32_t sA = st;
        const uint32_t sB = st + TILEB;

#pragma unroll
        for (int ks = 0; ks < 2; ks++) {
            uint32_t af[2][4];
            const int aRow = warpM * 32 + (lane & 15);
            const int aCh  = ks * 2 + (lane >> 4);
#pragma unroll
            for (int mt = 0; mt < 2; mt++)
                ldm4(af[mt], sA + gswz(aRow + mt * 16, aCh));
            uint32_t bf[4][4];
            const int bRow = warpN * 64 + ((lane >> 4) << 3) + (lane & 7);
            const int bCh  = ks * 2 + ((lane >> 3) & 1);
#pragma unroll
            for (int ntp = 0; ntp < 4; ntp++)
                ldm4(bf[ntp], sB + gswz(bRow + ntp * 16, bCh));
#pragma unroll
            for (int mt = 0; mt < 2; mt++)
#pragma unroll
                for (int nt = 0; nt < 8; nt++)
                    mma16816(acc[mt][nt], af[mt], &bf[nt >> 1][(nt & 1) * 2]);
        }
    }

    const int rBase = blockIdx.y * 128 + warpM * 32 + (lane >> 2);
    const int cBase = blockIdx.x * 128 + warpN * 64 + (lane & 3) * 2;
#pragma unroll
    for (int mt = 0; mt < 2; mt++) {
#pragma unroll
        for (int nt = 0; nt < 8; nt++) {
            const int gc = cBase + nt * 8;
            const float b0 = bias[gc], b1 = bias[gc + 1];
            const int r0 = rBase + mt * 16;
            float v00 = acc[mt][nt][0] + b0, v01 = acc[mt][nt][1] + b1;
            float v10 = acc[mt][nt][2] + b0, v11 = acc[mt][nt][3] + b1;
            if (out_mode == 0) {
                *(float2*)(C + (size_t)r0 * N + gc) = make_float2(v00, v01);
                *(float2*)(C + (size_t)(r0 + 8) * N + gc) = make_float2(v10, v11);
            } else {
                const float qs = (gc < 1024) ? QSCALE : 1.0f;
                *(uint32_t*)(Ch + (size_t)r0 * N + gc) = pk_hi2(v00 * qs, v01 * qs);
                *(uint32_t*)(Ch + (size_t)(r0 + 8) * N + gc) = pk_hi2(v10 * qs, v11 * qs);
            }
        }
    }
}

// ---------------------------------------------------------------------------
// HMMA flash attention (plain fp16 operands, fp32 accum, log2-domain softmax).
// q-tile 64, 4 warps / 128 threads, smem 40960B -> 4 CTAs/SM.
// S = Qh @ Kh (1 MMA); PV = Ph @ Vh (1 MMA). exp via ex2.approx (MUFU).
// ---------------------------------------------------------------------------
#define AQT      8192                    // 64 rows x 128B
#define AKVT     8192
#define ASTAGEB  (2 * AKVT)              // Kh, Vh = 16384
#define ATT_SMEM (AQT + 2 * ASTAGEB)     // 40960

__global__ __launch_bounds__(128, 4) void attn_mma(
    const __half* __restrict__ qkvh,
    __half* __restrict__ ch)
{
    extern __shared__ char smem[];
    const uint32_t sb = smem_u32(smem);
    const uint32_t sQ  = sb;
    const uint32_t sKV = sb + AQT;

    const int tid = threadIdx.x;
    const int lane = tid & 31;
    const int wid = tid >> 5;       // 0..3

    const int b = blockIdx.y >> 4;
    const int h = blockIdx.y & 15;
    const int q0 = blockIdx.x * 64;
    const size_t row0 = (size_t)b * SEQ;

    const size_t qoff = (row0 + q0) * 3072 + h * 64;
    const size_t koff = row0 * 3072 + 1024 + h * 64;
    const size_t voff = row0 * 3072 + 2048 + h * 64;

#pragma unroll
    for (int i = 0; i < 4; i++) {
        int idx = tid + i * 128;
        int row = idx >> 3, chk = idx & 7;
        cp16(sQ + aswz(row, chk), qkvh + qoff + (size_t)row * 3072 + chk * 8);
    }

    auto issueKV = [&](int t, int s) {
        const uint32_t st = sKV + s * ASTAGEB;
        const size_t kvrow = (size_t)t * 64;
#pragma unroll
        for (int i = 0; i < 4; i++) {
            int idx = tid + i * 128;
            int row = idx >> 3, chk = idx & 7;
            uint32_t so = aswz(row, chk);
            size_t go = (kvrow + row) * 3072 + chk * 8;
            cp16(st + 0 * AKVT + so, qkvh + koff + go);
            cp16(st + 1 * AKVT + so, qkvh + voff + go);
        }
    };
    issueKV(0, 0);
    CP_COMMIT();

    float o[8][4] = {};
    float mA = -1e30f, mB = -1e30f, lA = 0.f, lB = 0.f;

    const int bRow0 = ((lane >> 4) << 3) + (lane & 7);
    const int bChSel = (lane >> 3) & 1;

    const int NT = SEQ / 64;
    for (int t = 0; t < NT; t++) {
        CP_WAIT(0);
        __syncthreads();
        if (t + 1 < NT) { issueKV(t + 1, (t + 1) & 1); CP_COMMIT(); }

        const uint32_t st = sKV + (t & 1) * ASTAGEB;
        const uint32_t sKh = st;
        const uint32_t sVh = st + AKVT;

        // ---- S = Q K^T (plain fp16)
        float s[8][4] = {};
        const int aRow = wid * 16 + (lane & 15);
#pragma unroll
        for (int ks = 0; ks < 4; ks++) {
            uint32_t q4[4];
            ldm4(q4, sQ + aswz(aRow, ks * 2 + (lane >> 4)));
#pragma unroll
            for (int np = 0; np < 4; np++) {
                uint32_t k4[4];
                ldm4(k4, sKh + aswz(bRow0 + np * 16, ks * 2 + bChSel));
                mma16816(s[2 * np],     q4, &k4[0]);
                mma16816(s[2 * np + 1], q4, &k4[2]);
            }
        }

        // ---- online softmax (log2 domain; ex2.approx)
        float rmaxA = -1e30f, rmaxB = -1e30f;
#pragma unroll
        for (int nt = 0; nt < 8; nt++) {
            rmaxA = fmaxf(rmaxA, fmaxf(s[nt][0], s[nt][1]));
            rmaxB = fmaxf(rmaxB, fmaxf(s[nt][2], s[nt][3]));
        }
        rmaxA = fmaxf(rmaxA, __shfl_xor_sync(0xffffffffu, rmaxA, 1));
        rmaxA = fmaxf(rmaxA, __shfl_xor_sync(0xffffffffu, rmaxA, 2));
        rmaxB = fmaxf(rmaxB, __shfl_xor_sync(0xffffffffu, rmaxB, 1));
        rmaxB = fmaxf(rmaxB, __shfl_xor_sync(0xffffffffu, rmaxB, 2));

        float mnA = fmaxf(mA, rmaxA), mnB = fmaxf(mB, rmaxB);
        float corrA = ex2(mA - mnA), corrB = ex2(mB - mnB);
        mA = mnA; mB = mnB;

        float rsA = 0.f, rsB = 0.f;
#pragma unroll
        for (int nt = 0; nt < 8; nt++) {
            s[nt][0] = ex2(s[nt][0] - mnA);
            s[nt][1] = ex2(s[nt][1] - mnA);
            s[nt][2] = ex2(s[nt][2] - mnB);
            s[nt][3] = ex2(s[nt][3] - mnB);
            rsA += s[nt][0] + s[nt][1];
            rsB += s[nt][2] + s[nt][3];
        }
        rsA += __shfl_xor_sync(0xffffffffu, rsA, 1);
        rsA += __shfl_xor_sync(0xffffffffu, rsA, 2);
        rsB += __shfl_xor_sync(0xffffffffu, rsB, 1);
        rsB += __shfl_xor_sync(0xffffffffu, rsB, 2);
        lA = lA * corrA + rsA;
        lB = lB * corrB + rsB;
#pragma unroll
        for (int nt = 0; nt < 8; nt++) {
            o[nt][0] *= corrA; o[nt][1] *= corrA;
            o[nt][2] *= corrB; o[nt][3] *= corrB;
        }

        // ---- O += P V
#pragma unroll
        for (int t4 = 0; t4 < 4; t4++) {
            uint32_t ph[4];
            {
                const float* s0 = s[2 * t4];
                const float* s1 = s[2 * t4 + 1];
                ph[0] = pk_hi2(s0[0], s0[1]);
                ph[1] = pk_hi2(s0[2], s0[3]);
                ph[2] = pk_hi2(s1[0], s1[1]);
                ph[3] = pk_hi2(s1[2], s1[3]);
            }
            const int vRow = t4 * 16 + (lane & 15);
#pragma unroll
            for (int np = 0; np < 4; np++) {
                uint32_t vh[4];
                ldm4t(vh, sVh + aswz(vRow, np * 2 + (lane >> 4)));
                mma16816(o[2 * np],     ph, &vh[0]);
                mma16816(o[2 * np + 1], ph, &vh[2]);
            }
        }
    }

    // ---- epilogue: normalize, store ctx
    const float ivA = 1.f / lA, ivB = 1.f / lB;
    const size_t tokA = row0 + q0 + wid * 16 + (lane >> 2);
    const size_t tokB = tokA + 8;
#pragma unroll
    for (int nt = 0; nt < 8; nt++) {
        const int col = h * 64 + nt * 8 + (lane & 3) * 2;
        *(uint32_t*)(ch + tokA * D_MODEL + col) = pk_hi2(o[nt][0] * ivA, o[nt][1] * ivA);
        *(uint32_t*)(ch + tokB * D_MODEL + col) = pk_hi2(o[nt][2] * ivB, o[nt][3] * ivB);
    }
}

// ---------------------------------------------------------------------------
// Launch
// ---------------------------------------------------------------------------
extern "C" void kernel_launch(void* const* d_in, const int* in_sizes, int n_in,
                              void* d_out, int out_size)
{
    const float* x      = (const float*)d_in[0];
    const float* w_qkv  = (const float*)d_in[1];
    const float* b_qkv  = (const float*)d_in[2];
    const float* w_proj = (const float*)d_in[3];
    const float* b_proj = (const float*)d_in[4];
    float* out = (float*)d_out;

    __half *xh, *qkvh, *ch, *wqh, *wph;
    cudaGetSymbolAddress((void**)&xh, g_xh);
    cudaGetSymbolAddress((void**)&qkvh, g_qkvh);
    cudaGetSymbolAddress((void**)&ch, g_ch);
    cudaGetSymbolAddress((void**)&wqh, g_wqh);
    cudaGetSymbolAddress((void**)&wph, g_wph);

    cudaFuncSetAttribute(gemm_mma_f16,
                         cudaFuncAttributeMaxDynamicSharedMemorySize, GEMM_SMEM);
    cudaFuncSetAttribute(attn_mma,
                         cudaFuncAttributeMaxDynamicSharedMemorySize, ATT_SMEM);

    // 1) x -> fp16; weights transpose (fp16)
    {
        int n4 = NTOK * D_MODEL / 4;
        convert_hi<<<(n4 + 255) / 256, 256>>>((const float4*)x, (uint2*)xh, n4);
        dim3 tg(3 * D_MODEL / 32, D_MODEL / 32);
        transpose_hi<<<tg, dim3(32, 8)>>>(w_qkv, D_MODEL, 3 * D_MODEL, wqh);
        dim3 tp(D_MODEL / 32, D_MODEL / 32);
        transpose_hi<<<tp, dim3(32, 8)>>>(w_proj, D_MODEL, D_MODEL, wph);
    }

    // 2) QKV GEMM (plain fp16; Q cols get QSCALE) -> qkvh
    {
        dim3 grid(3 * D_MODEL / 128, NTOK / 128);
        gemm_mma_f16<<<grid, 256, GEMM_SMEM>>>(NTOK, 3 * D_MODEL, D_MODEL,
                                               xh, wqh, b_qkv,
                                               nullptr, qkvh, 1);
    }

    // 3) HMMA flash attention -> fp16 ctx
    {
        dim3 grid(SEQ / 64, BATCH * HEADS);
        attn_mma<<<grid, 128, ATT_SMEM>>>(qkvh, ch);
    }

    // 4) Proj GEMM (plain fp16) -> fp32 out
    {
        dim3 grid(D_MODEL / 128, NTOK / 128);
        gemm_mma_f16<<<grid, 256, GEMM_SMEM>>>(NTOK, D_MODEL, D_MODEL,
                                               ch, wph, b_proj,
                                               out, nullptr, 0);
    }
}

// round 17
// speedup vs baseline: 1.0435x; 1.0435x over previous
#include <cuda_runtime.h>
#include <cuda_fp16.h>
#include <cstdint>

#define D_MODEL 1024
#define HEADS   16
#define DH      64
#define BATCH   4
#define SEQ     2048
#define NTOK    (BATCH * SEQ)   // 8192

// Q pre-scale: 0.125 (dh^-1/2) * log2(e)  -> softmax done in base-2 domain
#define QSCALE 0.1803368801111204f

// ---------------- scratch (device globals; no runtime alloc allowed) -------
__device__ __half g_xh[(size_t)NTOK * D_MODEL];
__device__ __half g_qkvh[(size_t)NTOK * 3 * D_MODEL]; // [8192,3072]
__device__ __half g_ch[(size_t)NTOK * D_MODEL];       // ctx
__device__ __half g_wqh[(size_t)3 * D_MODEL * D_MODEL]; // Wqkv^T [3072,1024]
__device__ __half g_wph[(size_t)D_MODEL * D_MODEL];     // Wproj^T

// ---------------------------------------------------------------------------
// Helpers (portable ISA only — .target sm_103 without 'a')
// ---------------------------------------------------------------------------
__device__ __forceinline__ uint32_t smem_u32(const void* p) {
    uint32_t a;
    asm("{ .reg .u64 t; cvta.to.shared.u64 t, %1; cvt.u32.u64 %0, t; }"
        : "=r"(a) : "l"(p));
    return a;
}
__device__ __forceinline__ void cp16(uint32_t saddr, const void* gaddr) {
    asm volatile("cp.async.cg.shared.global [%0], [%1], 16;"
        :: "r"(saddr), "l"(gaddr));
}
#define CP_COMMIT() asm volatile("cp.async.commit_group;")
#define CP_WAIT(n)  asm volatile("cp.async.wait_group %0;" :: "n"(n))

__device__ __forceinline__ void ldm4(uint32_t* r, uint32_t a) {
    asm volatile("ldmatrix.sync.aligned.m8n8.x4.shared.b16 {%0,%1,%2,%3}, [%4];"
        : "=r"(r[0]), "=r"(r[1]), "=r"(r[2]), "=r"(r[3]) : "r"(a));
}
__device__ __forceinline__ void ldm4t(uint32_t* r, uint32_t a) {
    asm volatile("ldmatrix.sync.aligned.m8n8.x4.trans.shared.b16 {%0,%1,%2,%3}, [%4];"
        : "=r"(r[0]), "=r"(r[1]), "=r"(r[2]), "=r"(r[3]) : "r"(a));
}
__device__ __forceinline__ void mma16816(float* c, const uint32_t* a, const uint32_t* b) {
    asm volatile(
        "mma.sync.aligned.m16n8k16.row.col.f32.f16.f16.f32 "
        "{%0,%1,%2,%3}, {%4,%5,%6,%7}, {%8,%9}, {%0,%1,%2,%3};"
        : "+f"(c[0]), "+f"(c[1]), "+f"(c[2]), "+f"(c[3])
        : "r"(a[0]), "r"(a[1]), "r"(a[2]), "r"(a[3]), "r"(b[0]), "r"(b[1]));
}

__device__ __forceinline__ uint32_t pk_hi2(float a, float b) {
    __half2 hh = __floats2half2_rn(a, b);
    return *reinterpret_cast<uint32_t*>(&hh);
}

// fp32 MUFU exp2
__device__ __forceinline__ float ex2(float x) {
    float y;
    asm("ex2.approx.f32 %0, %1;" : "=f"(y) : "f"(x));
    return y;
}
// half2 MUFU exp2: one MUFU for two probabilities, result is the P fragment
__device__ __forceinline__ uint32_t ex2h2(uint32_t x) {
    uint32_t y;
    asm("ex2.approx.f16x2 %0, %1;" : "=r"(y) : "r"(x));
    return y;
}

// swizzled offset in a 32-col f16 tile (64B rows, 4 chunks)
__device__ __forceinline__ uint32_t gswz(int row, int chunk) {
    return (uint32_t)row * 64 + ((chunk ^ ((row >> 1) & 3)) << 4);
}
// swizzled offset in a 64-col f16 tile (128B rows, 8 chunks)
__device__ __forceinline__ uint32_t aswz(int row, int chunk) {
    return (uint32_t)row * 128 + ((chunk ^ (row & 7)) << 4);
}

// ---------------------------------------------------------------------------
// Conversion kernels
// ---------------------------------------------------------------------------
__global__ __launch_bounds__(256) void convert_hi(
    const float4* __restrict__ in, uint2* __restrict__ hi, int n4)
{
    int i = blockIdx.x * 256 + threadIdx.x;
    if (i >= n4) return;
    float4 v = in[i];
    hi[i] = make_uint2(pk_hi2(v.x, v.y), pk_hi2(v.z, v.w));
}

__global__ __launch_bounds__(256) void transpose_hi(
    const float* __restrict__ W, int K, int N, __half* __restrict__ Thi)
{
    __shared__ float tile[32][33];
    int kb = blockIdx.y * 32, nb = blockIdx.x * 32;
    int tx = threadIdx.x, ty = threadIdx.y;
#pragma unroll
    for (int i = 0; i < 32; i += 8)
        tile[ty + i][tx] = W[(size_t)(kb + ty + i) * N + nb + tx];
    __syncthreads();
#pragma unroll
    for (int i = 0; i < 32; i += 8) {
        int n = nb + ty + i, k = kb + tx;
        Thi[(size_t)n * K + k] = __float2half_rn(tile[tx][ty + i]);
    }
}

// ---------------------------------------------------------------------------
// HMMA fp16 GEMM: C = A[M,K] @ B[N,K]^T + bias  (fp32 accumulate)
// out_mode 0: fp32 C. out_mode 1: fp16 out, cols<1024 scaled by QSCALE (QKV).
// 128x128 CTA tile, K-chunk 32, swizzled 64B rows, 4-stage, 1 sync/iter.
// (unchanged from round 15 — measured best)
// ---------------------------------------------------------------------------
#define TILEB    8192
#define NSTAGE   4
#define STB      (2 * TILEB)
#define GEMM_SMEM (NSTAGE * STB)   // 65536

__global__ __launch_bounds__(256, 2) void gemm_mma_f16(
    int M, int N, int K,
    const __half* __restrict__ A,
    const __half* __restrict__ B,
    const float* __restrict__ bias,
    float* __restrict__ C,
    __half* __restrict__ Ch,
    int out_mode)
{
    extern __shared__ char smem[];
    const uint32_t sb = smem_u32(smem);

    const int tid = threadIdx.x;
    const int lane = tid & 31;
    const int wid = tid >> 5;
    const int warpM = wid & 3;
    const int warpN = wid >> 2;

    const size_t arow0 = (size_t)blockIdx.y * 128 * K;
    const size_t brow0 = (size_t)blockIdx.x * 128 * K;

    const int ldRow = tid >> 2;
    const int ldCh  = tid & 3;

    float acc[2][8][4] = {};
    const int NCH = K / 32;

    auto issue = [&](int c, int s) {
        const int k0 = c * 32;
        const uint32_t st = sb + s * STB;
#pragma unroll
        for (int p = 0; p < 2; p++) {
            const int row = ldRow + p * 64;
            const uint32_t soff = gswz(row, ldCh);
            const size_t goff = (size_t)row * K + k0 + ldCh * 8;
            cp16(st + soff, A + arow0 + goff);
            cp16(st + TILEB + soff, B + brow0 + goff);
        }
    };

    issue(0, 0); CP_COMMIT();
    issue(1, 1); CP_COMMIT();
    issue(2, 2); CP_COMMIT();

    for (int c = 0; c < NCH; c++) {
        if (c + 2 < NCH) CP_WAIT(2);
        else if (c + 1 < NCH) CP_WAIT(1);
        else CP_WAIT(0);
        __syncthreads();
        if (c + 3 < NCH) { issue(c + 3, (c + 3) % NSTAGE); CP_COMMIT(); }

        const uint32_t st = sb + (c % NSTAGE) * STB;
        const uint32_t sA = st;
        const uint32_t sB = st + TILEB;

#pragma unroll
        for (int ks = 0; ks < 2; ks++) {
            uint32_t af[2][4];
            const int aRow = warpM * 32 + (lane & 15);
            const int aCh  = ks * 2 + (lane >> 4);
#pragma unroll
            for (int mt = 0; mt < 2; mt++)
                ldm4(af[mt], sA + gswz(aRow + mt * 16, aCh));
            uint32_t bf[4][4];
            const int bRow = warpN * 64 + ((lane >> 4) << 3) + (lane & 7);
            const int bCh  = ks * 2 + ((lane >> 3) & 1);
#pragma unroll
            for (int ntp = 0; ntp < 4; ntp++)
                ldm4(bf[ntp], sB + gswz(bRow + ntp * 16, bCh));
#pragma unroll
            for (int mt = 0; mt < 2; mt++)
#pragma unroll
                for (int nt = 0; nt < 8; nt++)
                    mma16816(acc[mt][nt], af[mt], &bf[nt >> 1][(nt & 1) * 2]);
        }
    }

    const int rBase = blockIdx.y * 128 + warpM * 32 + (lane >> 2);
    const int cBase = blockIdx.x * 128 + warpN * 64 + (lane & 3) * 2;
#pragma unroll
    for (int mt = 0; mt < 2; mt++) {
#pragma unroll
        for (int nt = 0; nt < 8; nt++) {
            const int gc = cBase + nt * 8;
            const float b0 = bias[gc], b1 = bias[gc + 1];
            const int r0 = rBase + mt * 16;
            float v00 = acc[mt][nt][0] + b0, v01 = acc[mt][nt][1] + b1;
            float v10 = acc[mt][nt][2] + b0, v11 = acc[mt][nt][3] + b1;
            if (out_mode == 0) {
                *(float2*)(C + (size_t)r0 * N + gc) = make_float2(v00, v01);
                *(float2*)(C + (size_t)(r0 + 8) * N + gc) = make_float2(v10, v11);
            } else {
                const float qs = (gc < 1024) ? QSCALE : 1.0f;
                *(uint32_t*)(Ch + (size_t)r0 * N + gc) = pk_hi2(v00 * qs, v01 * qs);
                *(uint32_t*)(Ch + (size_t)(r0 + 8) * N + gc) = pk_hi2(v10 * qs, v11 * qs);
            }
        }
    }
}

// ---------------------------------------------------------------------------
// HMMA flash attention (fp16, log2 softmax via ex2.approx.f16x2).
// q-tile 64, 4 warps / 128 threads, smem 40960B -> 4 CTAs/SM.
// P fragments produced directly by half2 exp; row-sums via MMA-with-ones;
// o-rescale skipped when the running max is unchanged (warp-uniform branch).
// ---------------------------------------------------------------------------
#define AQT      8192                    // 64 rows x 128B
#define AKVT     8192
#define ASTAGEB  (2 * AKVT)              // Kh, Vh = 16384
#define ATT_SMEM (AQT + 2 * ASTAGEB)     // 40960

__global__ __launch_bounds__(128, 4) void attn_mma(
    const __half* __restrict__ qkvh,
    __half* __restrict__ ch)
{
    extern __shared__ char smem[];
    const uint32_t sb = smem_u32(smem);
    const uint32_t sQ  = sb;
    const uint32_t sKV = sb + AQT;

    const int tid = threadIdx.x;
    const int lane = tid & 31;
    const int wid = tid >> 5;       // 0..3

    const int b = blockIdx.y >> 4;
    const int h = blockIdx.y & 15;
    const int q0 = blockIdx.x * 64;
    const size_t row0 = (size_t)b * SEQ;

    const size_t qoff = (row0 + q0) * 3072 + h * 64;
    const size_t koff = row0 * 3072 + 1024 + h * 64;
    const size_t voff = row0 * 3072 + 2048 + h * 64;

#pragma unroll
    for (int i = 0; i < 4; i++) {
        int idx = tid + i * 128;
        int row = idx >> 3, chk = idx & 7;
        cp16(sQ + aswz(row, chk), qkvh + qoff + (size_t)row * 3072 + chk * 8);
    }

    auto issueKV = [&](int t, int s) {
        const uint32_t st = sKV + s * ASTAGEB;
        const size_t kvrow = (size_t)t * 64;
#pragma unroll
        for (int i = 0; i < 4; i++) {
            int idx = tid + i * 128;
            int row = idx >> 3, chk = idx & 7;
            uint32_t so = aswz(row, chk);
            size_t go = (kvrow + row) * 3072 + chk * 8;
            cp16(st + 0 * AKVT + so, qkvh + koff + go);
            cp16(st + 1 * AKVT + so, qkvh + voff + go);
        }
    };
    issueKV(0, 0);
    CP_COMMIT();

    float o[8][4] = {};
    float mA = -1e30f, mB = -1e30f, lA = 0.f, lB = 0.f;

    const uint32_t ONESB[2] = {0x3C003C00u, 0x3C003C00u};  // half2(1,1) x2

    const int bRow0 = ((lane >> 4) << 3) + (lane & 7);
    const int bChSel = (lane >> 3) & 1;

    const int NT = SEQ / 64;
    for (int t = 0; t < NT; t++) {
        CP_WAIT(0);
        __syncthreads();
        if (t + 1 < NT) { issueKV(t + 1, (t + 1) & 1); CP_COMMIT(); }

        const uint32_t st = sKV + (t & 1) * ASTAGEB;
        const uint32_t sKh = st;
        const uint32_t sVh = st + AKVT;

        // ---- S = Q K^T (plain fp16)
        float s[8][4] = {};
        const int aRow = wid * 16 + (lane & 15);
#pragma unroll
        for (int ks = 0; ks < 4; ks++) {
            uint32_t q4[4];
            ldm4(q4, sQ + aswz(aRow, ks * 2 + (lane >> 4)));
#pragma unroll
            for (int np = 0; np < 4; np++) {
                uint32_t k4[4];
                ldm4(k4, sKh + aswz(bRow0 + np * 16, ks * 2 + bChSel));
                mma16816(s[2 * np],     q4, &k4[0]);
                mma16816(s[2 * np + 1], q4, &k4[2]);
            }
        }

        // ---- online softmax (log2 domain)
        float rmaxA = -1e30f, rmaxB = -1e30f;
#pragma unroll
        for (int nt = 0; nt < 8; nt++) {
            rmaxA = fmaxf(rmaxA, fmaxf(s[nt][0], s[nt][1]));
            rmaxB = fmaxf(rmaxB, fmaxf(s[nt][2], s[nt][3]));
        }
        rmaxA = fmaxf(rmaxA, __shfl_xor_sync(0xffffffffu, rmaxA, 1));
        rmaxA = fmaxf(rmaxA, __shfl_xor_sync(0xffffffffu, rmaxA, 2));
        rmaxB = fmaxf(rmaxB, __shfl_xor_sync(0xffffffffu, rmaxB, 1));
        rmaxB = fmaxf(rmaxB, __shfl_xor_sync(0xffffffffu, rmaxB, 2));

        const float mnA = fmaxf(mA, rmaxA), mnB = fmaxf(mB, rmaxB);
        // warp-uniform skip: corr == 1 exactly when max unchanged
        if (__any_sync(0xffffffffu, (mnA != mA) || (mnB != mB))) {
            const float corrA = ex2(mA - mnA), corrB = ex2(mB - mnB);
            lA *= corrA; lB *= corrB;
#pragma unroll
            for (int nt = 0; nt < 8; nt++) {
                o[nt][0] *= corrA; o[nt][1] *= corrA;
                o[nt][2] *= corrB; o[nt][3] *= corrB;
            }
            mA = mnA; mB = mnB;
        }

        // ---- P = exp2(s - m) directly into fp16 fragments (half2 MUFU)
        uint32_t ph[4][4];
#pragma unroll
        for (int t4 = 0; t4 < 4; t4++) {
            const float* s0 = s[2 * t4];
            const float* s1 = s[2 * t4 + 1];
            ph[t4][0] = ex2h2(pk_hi2(s0[0] - mA, s0[1] - mA));
            ph[t4][1] = ex2h2(pk_hi2(s0[2] - mB, s0[3] - mB));
            ph[t4][2] = ex2h2(pk_hi2(s1[0] - mA, s1[1] - mA));
            ph[t4][3] = ex2h2(pk_hi2(s1[2] - mB, s1[3] - mB));
        }

        // ---- row sums via MMA with ones (fp32 accum of the actual fp16 P)
        float sums[4] = {};
#pragma unroll
        for (int t4 = 0; t4 < 4; t4++)
            mma16816(sums, ph[t4], ONESB);
        lA += sums[0];
        lB += sums[2];

        // ---- O += P V
#pragma unroll
        for (int t4 = 0; t4 < 4; t4++) {
            const int vRow = t4 * 16 + (lane & 15);
#pragma unroll
            for (int np = 0; np < 4; np++) {
                uint32_t vh[4];
                ldm4t(vh, sVh + aswz(vRow, np * 2 + (lane >> 4)));
                mma16816(o[2 * np],     ph[t4], &vh[0]);
                mma16816(o[2 * np + 1], ph[t4], &vh[2]);
            }
        }
    }

    // ---- epilogue: normalize, store ctx
    const float ivA = 1.f / lA, ivB = 1.f / lB;
    const size_t tokA = row0 + q0 + wid * 16 + (lane >> 2);
    const size_t tokB = tokA + 8;
#pragma unroll
    for (int nt = 0; nt < 8; nt++) {
        const int col = h * 64 + nt * 8 + (lane & 3) * 2;
        *(uint32_t*)(ch + tokA * D_MODEL + col) = pk_hi2(o[nt][0] * ivA, o[nt][1] * ivA);
        *(uint32_t*)(ch + tokB * D_MODEL + col) = pk_hi2(o[nt][2] * ivB, o[nt][3] * ivB);
    }
}

// ---------------------------------------------------------------------------
// Launch
// ---------------------------------------------------------------------------
extern "C" void kernel_launch(void* const* d_in, const int* in_sizes, int n_in,
                              void* d_out, int out_size)
{
    const float* x      = (const float*)d_in[0];
    const float* w_qkv  = (const float*)d_in[1];
    const float* b_qkv  = (const float*)d_in[2];
    const float* w_proj = (const float*)d_in[3];
    const float* b_proj = (const float*)d_in[4];
    float* out = (float*)d_out;

    __half *xh, *qkvh, *ch, *wqh, *wph;
    cudaGetSymbolAddress((void**)&xh, g_xh);
    cudaGetSymbolAddress((void**)&qkvh, g_qkvh);
    cudaGetSymbolAddress((void**)&ch, g_ch);
    cudaGetSymbolAddress((void**)&wqh, g_wqh);
    cudaGetSymbolAddress((void**)&wph, g_wph);

    cudaFuncSetAttribute(gemm_mma_f16,
                         cudaFuncAttributeMaxDynamicSharedMemorySize, GEMM_SMEM);
    cudaFuncSetAttribute(attn_mma,
                         cudaFuncAttributeMaxDynamicSharedMemorySize, ATT_SMEM);

    // 1) x -> fp16; weights transpose (fp16)
    {
        int n4 = NTOK * D_MODEL / 4;
        convert_hi<<<(n4 + 255) / 256, 256>>>((const float4*)x, (uint2*)xh, n4);
        dim3 tg(3 * D_MODEL / 32, D_MODEL / 32);
        transpose_hi<<<tg, dim3(32, 8)>>>(w_qkv, D_MODEL, 3 * D_MODEL, wqh);
        dim3 tp(D_MODEL / 32, D_MODEL / 32);
        transpose_hi<<<tp, dim3(32, 8)>>>(w_proj, D_MODEL, D_MODEL, wph);
    }

    // 2) QKV GEMM (plain fp16; Q cols get QSCALE) -> qkvh
    {
        dim3 grid(3 * D_MODEL / 128, NTOK / 128);
        gemm_mma_f16<<<grid, 256, GEMM_SMEM>>>(NTOK, 3 * D_MODEL, D_MODEL,
                                               xh, wqh, b_qkv,
                                               nullptr, qkvh, 1);
    }

    // 3) HMMA flash attention -> fp16 ctx
    {
        dim3 grid(SEQ / 64, BATCH * HEADS);
        attn_mma<<<grid, 128, ATT_SMEM>>>(qkvh, ch);
    }

    // 4) Proj GEMM (plain fp16) -> fp32 out
    {
        dim3 grid(D_MODEL / 128, NTOK / 128);
        gemm_mma_f16<<<grid, 256, GEMM_SMEM>>>(NTOK, D_MODEL, D_MODEL,
                                               ch, wph, b_proj,
                                               out, nullptr, 0);
    }
}